// round 6
// baseline (speedup 1.0000x reference)
#include <cuda_runtime.h>
#include <cuda_bf16.h>
#include <cstdint>

// ============================================================================
// out[b,n,m] = <x[b,n,:], y[b,m,:]> / max(||x[b,n]|| * ||y[b,m]||, eps)
//   x, y: [8, 2048, 512] fp32 ; out: [8, 2048, 2048] fp32
//
// Round 6: mixed-precision 3-term split with fp8 cross terms.
//   dot = hi_a*hi_b (bf16 HMMA) + hi8_a*lo8_b + lo8_a*hi8_b (fp8 QMMA, 2x rate)
//   hi  = bf16_rn(x); hi8 = e4m3(hi); lo8 = e5m2(x - hi)
//   CTA 128x256, 512 threads, warp tile 64x32, 2-stage cp.async (BK=64).
// ============================================================================

#define Bq 8
#define Nq 2048
#define Dq 512
#define EPSq 1e-8f

#define BMq 128
#define BNq 256
#define BKq 64
#define KITER (Dq / BKq)       // 8

// per-stage: Ahi 16K | Ahi8 8K | Alo8 8K | Bhi 32K | Bhi8 16K | Blo8 16K = 96K
#define A_HI_OFF   0
#define A_HI8_OFF  16384
#define A_LO8_OFF  24576
#define B_HI_OFF   32768
#define B_HI8_OFF  65536
#define B_LO8_OFF  81920
#define STG_BYTES  98304
#define SMEM_TOTAL (2 * STG_BYTES)   // 196608

__device__ float g_xn[Bq * Nq];
__device__ float g_yn[Bq * Nq];
__device__ __nv_bfloat16 g_xhi[Bq * Nq * Dq];
__device__ __nv_bfloat16 g_yhi[Bq * Nq * Dq];
__device__ uint8_t g_xhi8[Bq * Nq * Dq];
__device__ uint8_t g_xlo8[Bq * Nq * Dq];
__device__ uint8_t g_yhi8[Bq * Nq * Dq];
__device__ uint8_t g_ylo8[Bq * Nq * Dq];

// ---------------------------------------------------------------------------
__device__ __forceinline__ uint32_t smem_u32(const void* p) {
    uint32_t a;
    asm("{ .reg .u64 t; cvta.to.shared.u64 t, %1; cvt.u32.u64 %0, t; }"
        : "=r"(a) : "l"(p));
    return a;
}

#define CP_ASYNC16(dst, src) \
    asm volatile("cp.async.cg.shared.global [%0], [%1], 16;" \
                 :: "r"(dst), "l"(src) : "memory")
#define CP_COMMIT() asm volatile("cp.async.commit_group;" ::: "memory")
#define CP_WAIT1()  asm volatile("cp.async.wait_group 1;" ::: "memory")

#define LDSM4(r, addr) \
    asm volatile("ldmatrix.sync.aligned.m8n8.x4.shared.b16 {%0,%1,%2,%3}, [%4];" \
                 : "=r"((r)[0]), "=r"((r)[1]), "=r"((r)[2]), "=r"((r)[3]) \
                 : "r"(addr))

#define MMA_BF16(d, a, bf) \
    asm volatile("mma.sync.aligned.m16n8k16.row.col.f32.bf16.bf16.f32 " \
                 "{%0,%1,%2,%3}, {%4,%5,%6,%7}, {%8,%9}, {%0,%1,%2,%3};" \
                 : "+f"((d)[0]), "+f"((d)[1]), "+f"((d)[2]), "+f"((d)[3]) \
                 : "r"((a)[0]), "r"((a)[1]), "r"((a)[2]), "r"((a)[3]), \
                   "r"((bf)[0]), "r"((bf)[1]))

// fp8 k32: A = e4m3 (hi8), B = e5m2 (lo8)
#define MMA_F8_HL(d, a, bf) \
    asm volatile("mma.sync.aligned.m16n8k32.row.col.f32.e4m3.e5m2.f32 " \
                 "{%0,%1,%2,%3}, {%4,%5,%6,%7}, {%8,%9}, {%0,%1,%2,%3};" \
                 : "+f"((d)[0]), "+f"((d)[1]), "+f"((d)[2]), "+f"((d)[3]) \
                 : "r"((a)[0]), "r"((a)[1]), "r"((a)[2]), "r"((a)[3]), \
                   "r"((bf)[0]), "r"((bf)[1]))

// fp8 k32: A = e5m2 (lo8), B = e4m3 (hi8)
#define MMA_F8_LH(d, a, bf) \
    asm volatile("mma.sync.aligned.m16n8k32.row.col.f32.e5m2.e4m3.f32 " \
                 "{%0,%1,%2,%3}, {%4,%5,%6,%7}, {%8,%9}, {%0,%1,%2,%3};" \
                 : "+f"((d)[0]), "+f"((d)[1]), "+f"((d)[2]), "+f"((d)[3]) \
                 : "r"((a)[0]), "r"((a)[1]), "r"((a)[2]), "r"((a)[3]), \
                   "r"((bf)[0]), "r"((bf)[1]))

// fp8 pack: first float -> HIGH byte, second -> LOW byte (bf16x2 convention)
#define CVT_E4M3X2(d, hi, lo) \
    asm("cvt.rn.satfinite.e4m3x2.f32 %0, %1, %2;" : "=h"(d) : "f"(hi), "f"(lo))
#define CVT_E5M2X2(d, hi, lo) \
    asm("cvt.rn.satfinite.e5m2x2.f32 %0, %1, %2;" : "=h"(d) : "f"(hi), "f"(lo))

// paired-row swizzle for 64B rows: line = r>>1 (128B), ce = (r&1)*4 + c
__device__ __forceinline__ uint32_t swz64(int r, int c) {
    uint32_t line = (uint32_t)r >> 1;
    uint32_t ce = (((uint32_t)r & 1u) << 2) | (uint32_t)c;
    return line * 128u + ((ce ^ (line & 7u)) << 4);
}

// ---------------------------------------------------------------------------
// Prep: one warp per row: norms + bf16 hi + fp8 (hi8 e4m3, lo8 e5m2).
// ---------------------------------------------------------------------------
__device__ __forceinline__ void split_store(const float4& a, size_t off,
                                            __nv_bfloat16* hi_arr,
                                            uint8_t* hi8_arr, uint8_t* lo8_arr) {
    __nv_bfloat162 h0 = __floats2bfloat162_rn(a.x, a.y);
    __nv_bfloat162 h1 = __floats2bfloat162_rn(a.z, a.w);
    float f0 = __bfloat162float(h0.x), f1 = __bfloat162float(h0.y);
    float f2 = __bfloat162float(h1.x), f3 = __bfloat162float(h1.y);
    *reinterpret_cast<__nv_bfloat162*>(hi_arr + off)     = h0;
    *reinterpret_cast<__nv_bfloat162*>(hi_arr + off + 2) = h1;
    uint16_t p01, p23;
    CVT_E4M3X2(p01, f1, f0);
    CVT_E4M3X2(p23, f3, f2);
    *reinterpret_cast<uint32_t*>(hi8_arr + off) = (uint32_t)p01 | ((uint32_t)p23 << 16);
    float r0 = a.x - f0, r1 = a.y - f1, r2 = a.z - f2, r3 = a.w - f3;
    CVT_E5M2X2(p01, r1, r0);
    CVT_E5M2X2(p23, r3, r2);
    *reinterpret_cast<uint32_t*>(lo8_arr + off) = (uint32_t)p01 | ((uint32_t)p23 << 16);
}

__global__ void __launch_bounds__(256) prep_kernel(const float* __restrict__ X,
                                                   const float* __restrict__ Y) {
    int row = blockIdx.x * 8 + (threadIdx.x >> 5);
    int lane = threadIdx.x & 31;
    if (row >= Bq * Nq) return;

    const float4* px = reinterpret_cast<const float4*>(X + (size_t)row * Dq);
    const float4* py = reinterpret_cast<const float4*>(Y + (size_t)row * Dq);

    float sx = 0.f, sy = 0.f;
#pragma unroll
    for (int v = 0; v < 4; v++) {
        int i = v * 32 + lane;
        size_t off = (size_t)row * Dq + (size_t)i * 4;
        float4 a = px[i];
        sx = fmaf(a.x, a.x, sx); sx = fmaf(a.y, a.y, sx);
        sx = fmaf(a.z, a.z, sx); sx = fmaf(a.w, a.w, sx);
        split_store(a, off, g_xhi, g_xhi8, g_xlo8);
        float4 c = py[i];
        sy = fmaf(c.x, c.x, sy); sy = fmaf(c.y, c.y, sy);
        sy = fmaf(c.z, c.z, sy); sy = fmaf(c.w, c.w, sy);
        split_store(c, off, g_yhi, g_yhi8, g_ylo8);
    }
#pragma unroll
    for (int off = 16; off > 0; off >>= 1) {
        sx += __shfl_xor_sync(0xFFFFFFFFu, sx, off);
        sy += __shfl_xor_sync(0xFFFFFFFFu, sy, off);
    }
    if (lane == 0) {
        g_xn[row] = sqrtf(sx);
        g_yn[row] = sqrtf(sy);
    }
}

// ---------------------------------------------------------------------------
// cp.async one stage. bf16 tiles: 128B rows, swizzle c^(r&7) (c in 0..7).
// fp8 tiles: 64B rows, paired swizzle (c in 0..3). 512 threads, 12 cp/thread.
// ---------------------------------------------------------------------------
__device__ __forceinline__ void load_stage(uint32_t st, int kt,
                                           int rowA0, int rowB0, int b, int tid) {
    const size_t kb = (size_t)kt * BKq;
    // A hi bf16: 128 rows x 8 chunks
#pragma unroll
    for (int i = 0; i < 2; i++) {
        int idx = tid + i * 512;
        int r = idx >> 3, c = idx & 7;
        uint32_t doff = (uint32_t)r * 128 + (uint32_t)((c ^ (r & 7)) << 4);
        size_t off = ((size_t)(b * Nq + rowA0 + r)) * Dq + kb + c * 8;
        CP_ASYNC16(st + A_HI_OFF + doff, g_xhi + off);
    }
    // A fp8: 128 rows x 4 chunks each
    {
        int r = tid >> 2, c = tid & 3;
        uint32_t doff = swz64(r, c);
        size_t off = ((size_t)(b * Nq + rowA0 + r)) * Dq + kb + c * 16;
        CP_ASYNC16(st + A_HI8_OFF + doff, g_xhi8 + off);
        CP_ASYNC16(st + A_LO8_OFF + doff, g_xlo8 + off);
    }
    // B hi bf16: 256 rows x 8 chunks
#pragma unroll
    for (int i = 0; i < 4; i++) {
        int idx = tid + i * 512;
        int r = idx >> 3, c = idx & 7;
        uint32_t doff = (uint32_t)r * 128 + (uint32_t)((c ^ (r & 7)) << 4);
        size_t off = ((size_t)(b * Nq + rowB0 + r)) * Dq + kb + c * 8;
        CP_ASYNC16(st + B_HI_OFF + doff, g_yhi + off);
    }
    // B fp8: 256 rows x 4 chunks each
#pragma unroll
    for (int i = 0; i < 2; i++) {
        int idx = tid + i * 512;
        int r = idx >> 2, c = idx & 3;
        uint32_t doff = swz64(r, c);
        size_t off = ((size_t)(b * Nq + rowB0 + r)) * Dq + kb + c * 16;
        CP_ASYNC16(st + B_HI8_OFF + doff, g_yhi8 + off);
        CP_ASYNC16(st + B_LO8_OFF + doff, g_ylo8 + off);
    }
}

// ---------------------------------------------------------------------------
// GEMM. Grid (8,16,8), 512 threads = 16 warps (2x8), warp tile 64x32.
// ---------------------------------------------------------------------------
__global__ void __launch_bounds__(512, 1) cosine_mma_kernel(float* __restrict__ out) {
    extern __shared__ char smem[];
    const uint32_t sb = smem_u32(smem);

    const int tid = threadIdx.x;
    const int wid = tid >> 5, lane = tid & 31;
    const int wm = wid >> 3;          // 0..1
    const int wn = wid & 7;           // 0..7
    const int tileM = blockIdx.x;
    const int tileN = blockIdx.y;
    const int b = blockIdx.z;
    const int rowA0 = tileN * BMq;
    const int rowB0 = tileM * BNq;

    float acc[4][4][4];
#pragma unroll
    for (int i = 0; i < 4; i++)
#pragma unroll
        for (int j = 0; j < 4; j++)
#pragma unroll
            for (int r = 0; r < 4; r++) acc[i][j][r] = 0.f;

    load_stage(sb + 0 * STG_BYTES, 0, rowA0, rowB0, b, tid); CP_COMMIT();
    load_stage(sb + 1 * STG_BYTES, 1, rowA0, rowB0, b, tid); CP_COMMIT();

    const int rowSel = (lane & 7) + (((lane >> 3) & 1) << 3);  // 0..15
    const uint32_t kcq = (uint32_t)(lane >> 4);                // 0/1

    // hoisted address pieces
    uint32_t aRowT[4], aSwz[4], aLine[4], aPar[4], aSwz8[4];
#pragma unroll
    for (int mi = 0; mi < 4; mi++) {
        int row = wm * 64 + mi * 16 + rowSel;
        aRowT[mi] = (uint32_t)row * 128u;
        aSwz[mi]  = ((uint32_t)row & 7u) << 4;
        aLine[mi] = (uint32_t)(row >> 1) * 128u;
        aPar[mi]  = ((uint32_t)row & 1u) << 2;
        aSwz8[mi] = (uint32_t)(row >> 1) & 7u;
    }
    uint32_t bRowT[2], bSwz[2], bLine[2], bPar[2], bSwz8[2];
#pragma unroll
    for (int nj = 0; nj < 2; nj++) {
        int row = wn * 32 + nj * 16 + rowSel;
        bRowT[nj] = (uint32_t)row * 128u;
        bSwz[nj]  = ((uint32_t)row & 7u) << 4;
        bLine[nj] = (uint32_t)(row >> 1) * 128u;
        bPar[nj]  = ((uint32_t)row & 1u) << 2;
        bSwz8[nj] = (uint32_t)(row >> 1) & 7u;
    }

    for (int t = 0; t < KITER; t++) {
        CP_WAIT1();
        __syncthreads();

        const uint32_t st = sb + (t & 1) * STG_BYTES;
        const uint32_t sAhi = st + A_HI_OFF, sAhi8 = st + A_HI8_OFF, sAlo8 = st + A_LO8_OFF;
        const uint32_t sBhi = st + B_HI_OFF, sBhi8 = st + B_HI8_OFF, sBlo8 = st + B_LO8_OFF;

#pragma unroll
        for (int kc8 = 0; kc8 < 2; kc8++) {     // two k32 blocks per stage
            const uint32_t c8 = (uint32_t)(kc8 * 2) + kcq;   // fp8 16B chunk 0..3

            // --- B fp8 fragments (k32): hi8, lo8 ---
            uint32_t b_hi8[4][2], b_lo8[4][2];
#pragma unroll
            for (int nj = 0; nj < 2; nj++) {
                uint32_t off = bLine[nj] + (((bPar[nj] | c8) ^ bSwz8[nj]) << 4);
                uint32_t th[4], tl[4];
                LDSM4(th, sBhi8 + off);
                LDSM4(tl, sBlo8 + off);
                b_hi8[2 * nj][0] = th[0]; b_hi8[2 * nj][1] = th[2];
                b_hi8[2 * nj + 1][0] = th[1]; b_hi8[2 * nj + 1][1] = th[3];
                b_lo8[2 * nj][0] = tl[0]; b_lo8[2 * nj][1] = tl[2];
                b_lo8[2 * nj + 1][0] = tl[1]; b_lo8[2 * nj + 1][1] = tl[3];
            }

            // --- hh pass, k16 halves sequentially (reuses B bf16 regs) ---
#pragma unroll
            for (int kh = 0; kh < 2; kh++) {
                const uint32_t kc16 = (uint32_t)((kc8 * 2 + kh) * 2) + kcq;  // 0..7
                uint32_t b_hi[4][2];
#pragma unroll
                for (int nj = 0; nj < 2; nj++) {
                    uint32_t off = bRowT[nj] + (((kc16 << 4)) ^ bSwz[nj]);
                    uint32_t th[4];
                    LDSM4(th, sBhi + off);
                    b_hi[2 * nj][0] = th[0]; b_hi[2 * nj][1] = th[2];
                    b_hi[2 * nj + 1][0] = th[1]; b_hi[2 * nj + 1][1] = th[3];
                }
#pragma unroll
                for (int mi = 0; mi < 4; mi++) {
                    uint32_t a_hi[4];
                    uint32_t off = aRowT[mi] + ((kc16 << 4) ^ aSwz[mi]);
                    LDSM4(a_hi, sAhi + off);
#pragma unroll
                    for (int ni = 0; ni < 4; ni++) MMA_BF16(acc[mi][ni], a_hi, b_hi[ni]);
                }
            }

            // --- cross passes (fp8 k32) ---
#pragma unroll
            for (int mi = 0; mi < 4; mi++) {
                uint32_t off = aLine[mi] + (((aPar[mi] | c8) ^ aSwz8[mi]) << 4);
                uint32_t a_hi8[4], a_lo8[4];
                LDSM4(a_hi8, sAhi8 + off);
                LDSM4(a_lo8, sAlo8 + off);
#pragma unroll
                for (int ni = 0; ni < 4; ni++) MMA_F8_HL(acc[mi][ni], a_hi8, b_lo8[ni]);
#pragma unroll
                for (int ni = 0; ni < 4; ni++) MMA_F8_LH(acc[mi][ni], a_lo8, b_hi8[ni]);
            }
        }
        __syncthreads();
        if (t + 2 < KITER)
            load_stage(sb + (t & 1) * STG_BYTES, t + 2, rowA0, rowB0, b, tid);
        CP_COMMIT();
    }

    // ---- fused cosine epilogue ----
    const int gq = lane >> 2;
    const int tq = lane & 3;

    float yv0[4], yv1[4];
#pragma unroll
    for (int ni = 0; ni < 4; ni++) {
        int n = rowB0 + wn * 32 + ni * 8 + 2 * tq;
        yv0[ni] = g_yn[b * Nq + n];
        yv1[ni] = g_yn[b * Nq + n + 1];
    }

#pragma unroll
    for (int mi = 0; mi < 4; mi++) {
        int mA = rowA0 + wm * 64 + mi * 16 + gq;
        float xA = g_xn[b * Nq + mA];
        float xB = g_xn[b * Nq + mA + 8];
        float* orowA = out + ((size_t)b * Nq + mA) * Nq + rowB0 + wn * 32;
        float* orowB = orowA + 8 * (size_t)Nq;
#pragma unroll
        for (int ni = 0; ni < 4; ni++) {
            float2 vA, vB;
            vA.x = acc[mi][ni][0] / fmaxf(xA * yv0[ni], EPSq);
            vA.y = acc[mi][ni][1] / fmaxf(xA * yv1[ni], EPSq);
            vB.x = acc[mi][ni][2] / fmaxf(xB * yv0[ni], EPSq);
            vB.y = acc[mi][ni][3] / fmaxf(xB * yv1[ni], EPSq);
            *reinterpret_cast<float2*>(orowA + ni * 8 + 2 * tq) = vA;
            *reinterpret_cast<float2*>(orowB + ni * 8 + 2 * tq) = vB;
        }
    }
}

// ---------------------------------------------------------------------------
extern "C" void kernel_launch(void* const* d_in, const int* in_sizes, int n_in,
                              void* d_out, int out_size) {
    const float* x = (const float*)d_in[0];
    const float* y = (const float*)d_in[1];
    float* out = (float*)d_out;

    prep_kernel<<<(Bq * Nq + 7) / 8, 256>>>(x, y);

    cudaFuncSetAttribute(cosine_mma_kernel,
                         cudaFuncAttributeMaxDynamicSharedMemorySize, SMEM_TOTAL);
    dim3 grid(Nq / BNq, Nq / BMq, Bq);   // (8, 16, 8)
    cosine_mma_kernel<<<grid, 512, SMEM_TOTAL>>>(out);
}

// round 8
// speedup vs baseline: 1.2033x; 1.2033x over previous
#include <cuda_runtime.h>
#include <cuda_bf16.h>
#include <cstdint>

// ============================================================================
// out[b,n,m] = <x[b,n,:], y[b,m,:]> / max(||x[b,n]|| * ||y[b,m]||, eps)
//   x, y: [8, 2048, 512] fp32 ; out: [8, 2048, 2048] fp32
//
// Round 8: bf16 Markidis 3-pass, 2 CTAs/SM. Fixes round 7's pipeline race:
//   3-stage ring, loads for k-tile t+3 issued AFTER compute(t) + barrier
//   (stage t%3 overwrite is then safe). Round-4-proven ordering.
//   CTA 128x128, 256 threads, BK=32, 96KB smem, 128 regs -> 2 CTAs/SM.
// ============================================================================

#define Bq 8
#define Nq 2048
#define Dq 512
#define EPSq 1e-8f

#define BMq 128
#define BNq 128
#define BKq 32
#define KITER (Dq / BKq)       // 16

// per-stage: Ahi 8K | Alo 8K | Bhi 8K | Blo 8K = 32KB; 3 stages = 96KB
#define A_HI_OFF   0
#define A_LO_OFF   8192
#define B_HI_OFF   16384
#define B_LO_OFF   24576
#define STG_BYTES  32768
#define SMEM_TOTAL (3 * STG_BYTES)   // 98304

#define ROW64 (64 * Dq)        // 64-row pointer offset (elements)

__device__ float g_xn[Bq * Nq];
__device__ float g_yn[Bq * Nq];
__device__ __nv_bfloat16 g_xhi[Bq * Nq * Dq];
__device__ __nv_bfloat16 g_xlo[Bq * Nq * Dq];
__device__ __nv_bfloat16 g_yhi[Bq * Nq * Dq];
__device__ __nv_bfloat16 g_ylo[Bq * Nq * Dq];

// ---------------------------------------------------------------------------
__device__ __forceinline__ uint32_t smem_u32(const void* p) {
    uint32_t a;
    asm("{ .reg .u64 t; cvta.to.shared.u64 t, %1; cvt.u32.u64 %0, t; }"
        : "=r"(a) : "l"(p));
    return a;
}

#define CP_ASYNC16(dst, src) \
    asm volatile("cp.async.cg.shared.global [%0], [%1], 16;" \
                 :: "r"(dst), "l"(src) : "memory")
#define CP_COMMIT() asm volatile("cp.async.commit_group;" ::: "memory")
#define CP_WAIT2()  asm volatile("cp.async.wait_group 2;" ::: "memory")

#define LDSM4(r, addr) \
    asm volatile("ldmatrix.sync.aligned.m8n8.x4.shared.b16 {%0,%1,%2,%3}, [%4];" \
                 : "=r"((r)[0]), "=r"((r)[1]), "=r"((r)[2]), "=r"((r)[3]) \
                 : "r"(addr))

#define MMA16816(d, a, bf) \
    asm volatile("mma.sync.aligned.m16n8k16.row.col.f32.bf16.bf16.f32 " \
                 "{%0,%1,%2,%3}, {%4,%5,%6,%7}, {%8,%9}, {%0,%1,%2,%3};" \
                 : "+f"((d)[0]), "+f"((d)[1]), "+f"((d)[2]), "+f"((d)[3]) \
                 : "r"((a)[0]), "r"((a)[1]), "r"((a)[2]), "r"((a)[3]), \
                   "r"((bf)[0]), "r"((bf)[1]))

// paired-row swizzle for 64B rows: line = r>>1 (128B), ce = (r&1)*4 + c
__device__ __forceinline__ uint32_t swz64(int r, int c) {
    uint32_t line = (uint32_t)r >> 1;
    uint32_t ce = (((uint32_t)r & 1u) << 2) | (uint32_t)c;
    return line * 128u + ((ce ^ (line & 7u)) << 4);
}

// ---------------------------------------------------------------------------
// Prep: one warp per row: norms + hi/lo bf16 split.
// ---------------------------------------------------------------------------
__global__ void __launch_bounds__(256) prep_kernel(const float* __restrict__ X,
                                                   const float* __restrict__ Y) {
    int row = blockIdx.x * 8 + (threadIdx.x >> 5);
    int lane = threadIdx.x & 31;
    if (row >= Bq * Nq) return;

    const float4* px = reinterpret_cast<const float4*>(X + (size_t)row * Dq);
    const float4* py = reinterpret_cast<const float4*>(Y + (size_t)row * Dq);

    float sx = 0.f, sy = 0.f;
#pragma unroll
    for (int v = 0; v < 4; v++) {
        int i = v * 32 + lane;
        {
            float4 a = px[i];
            sx = fmaf(a.x, a.x, sx); sx = fmaf(a.y, a.y, sx);
            sx = fmaf(a.z, a.z, sx); sx = fmaf(a.w, a.w, sx);
            __nv_bfloat162 h0 = __floats2bfloat162_rn(a.x, a.y);
            __nv_bfloat162 h1 = __floats2bfloat162_rn(a.z, a.w);
            __nv_bfloat162 l0 = __floats2bfloat162_rn(a.x - __bfloat162float(h0.x),
                                                      a.y - __bfloat162float(h0.y));
            __nv_bfloat162 l1 = __floats2bfloat162_rn(a.z - __bfloat162float(h1.x),
                                                      a.w - __bfloat162float(h1.y));
            size_t off = (size_t)row * Dq + (size_t)i * 4;
            *reinterpret_cast<__nv_bfloat162*>(g_xhi + off)     = h0;
            *reinterpret_cast<__nv_bfloat162*>(g_xhi + off + 2) = h1;
            *reinterpret_cast<__nv_bfloat162*>(g_xlo + off)     = l0;
            *reinterpret_cast<__nv_bfloat162*>(g_xlo + off + 2) = l1;
        }
        {
            float4 a = py[i];
            sy = fmaf(a.x, a.x, sy); sy = fmaf(a.y, a.y, sy);
            sy = fmaf(a.z, a.z, sy); sy = fmaf(a.w, a.w, sy);
            __nv_bfloat162 h0 = __floats2bfloat162_rn(a.x, a.y);
            __nv_bfloat162 h1 = __floats2bfloat162_rn(a.z, a.w);
            __nv_bfloat162 l0 = __floats2bfloat162_rn(a.x - __bfloat162float(h0.x),
                                                      a.y - __bfloat162float(h0.y));
            __nv_bfloat162 l1 = __floats2bfloat162_rn(a.z - __bfloat162float(h1.x),
                                                      a.w - __bfloat162float(h1.y));
            size_t off = (size_t)row * Dq + (size_t)i * 4;
            *reinterpret_cast<__nv_bfloat162*>(g_yhi + off)     = h0;
            *reinterpret_cast<__nv_bfloat162*>(g_yhi + off + 2) = h1;
            *reinterpret_cast<__nv_bfloat162*>(g_ylo + off)     = l0;
            *reinterpret_cast<__nv_bfloat162*>(g_ylo + off + 2) = l1;
        }
    }
#pragma unroll
    for (int off = 16; off > 0; off >>= 1) {
        sx += __shfl_xor_sync(0xFFFFFFFFu, sx, off);
        sy += __shfl_xor_sync(0xFFFFFFFFu, sy, off);
    }
    if (lane == 0) {
        g_xn[row] = sqrtf(sx);
        g_yn[row] = sqrtf(sy);
    }
}

// ---------------------------------------------------------------------------
// GEMM kernel. Grid (16,16,8), 256 threads = 8 warps (2x4), warp tile 64x32.
// 2 CTAs per SM.
// ---------------------------------------------------------------------------
__global__ void __launch_bounds__(256, 2) cosine_mma_kernel(float* __restrict__ out) {
    extern __shared__ char smem[];
    const uint32_t sb = smem_u32(smem);

    const int tid = threadIdx.x;
    const int wid = tid >> 5, lane = tid & 31;
    const int wm = wid >> 2;          // 0..1  (64 m-rows)
    const int wn = wid & 3;           // 0..3  (32 n-cols)
    const int tileM = blockIdx.x;
    const int tileN = blockIdx.y;
    const int b = blockIdx.z;
    const int rowA0 = tileN * BMq;
    const int rowB0 = tileM * BNq;

    // ---- per-thread cp.async setup (pointer-increment addressing) ----
    const int r0 = tid >> 2;          // 0..63
    const int c0 = tid & 3;           // 16B chunk
    const uint32_t d0 = swz64(r0, c0);
    const uint32_t d1 = swz64(r0 + 64, c0);
    const __nv_bfloat16* pxh = g_xhi + (size_t)(b * Nq + rowA0 + r0) * Dq + c0 * 8;
    const __nv_bfloat16* pxl = g_xlo + (size_t)(b * Nq + rowA0 + r0) * Dq + c0 * 8;
    const __nv_bfloat16* pyh = g_yhi + (size_t)(b * Nq + rowB0 + r0) * Dq + c0 * 8;
    const __nv_bfloat16* pyl = g_ylo + (size_t)(b * Nq + rowB0 + r0) * Dq + c0 * 8;

#define LOAD_STAGE(ST) do {                                          \
        CP_ASYNC16((ST) + A_HI_OFF + d0, pxh);                       \
        CP_ASYNC16((ST) + A_HI_OFF + d1, pxh + ROW64);               \
        CP_ASYNC16((ST) + A_LO_OFF + d0, pxl);                       \
        CP_ASYNC16((ST) + A_LO_OFF + d1, pxl + ROW64);               \
        CP_ASYNC16((ST) + B_HI_OFF + d0, pyh);                       \
        CP_ASYNC16((ST) + B_HI_OFF + d1, pyh + ROW64);               \
        CP_ASYNC16((ST) + B_LO_OFF + d0, pyl);                       \
        CP_ASYNC16((ST) + B_LO_OFF + d1, pyl + ROW64);               \
        pxh += BKq; pxl += BKq; pyh += BKq; pyl += BKq;              \
    } while (0)

    float acc[4][4][4];
#pragma unroll
    for (int i = 0; i < 4; i++)
#pragma unroll
        for (int j = 0; j < 4; j++)
#pragma unroll
            for (int r = 0; r < 4; r++) acc[i][j][r] = 0.f;

    // prologue: 3 stages in flight (k-tiles 0,1,2)
    LOAD_STAGE(sb + 0 * STG_BYTES); CP_COMMIT();
    LOAD_STAGE(sb + 1 * STG_BYTES); CP_COMMIT();
    LOAD_STAGE(sb + 2 * STG_BYTES); CP_COMMIT();

    // ---- fragment addressing (round-5-verified swz64 layout) ----
    const int rowSel = (lane & 7) + (((lane >> 3) & 1) << 3);  // 0..15
    const uint32_t kcq = (uint32_t)(lane >> 4);                // 0/1

    uint32_t aLine[4], aPar[4], aSwz[4];
#pragma unroll
    for (int mi = 0; mi < 4; mi++) {
        int row = wm * 64 + mi * 16 + rowSel;
        aLine[mi] = (uint32_t)(row >> 1) * 128u;
        aPar[mi]  = ((uint32_t)row & 1u) << 2;
        aSwz[mi]  = (uint32_t)(row >> 1) & 7u;
    }
    uint32_t bLine[2], bPar[2], bSwz[2];
#pragma unroll
    for (int nj = 0; nj < 2; nj++) {
        int row = wn * 32 + nj * 16 + rowSel;
        bLine[nj] = (uint32_t)(row >> 1) * 128u;
        bPar[nj]  = ((uint32_t)row & 1u) << 2;
        bSwz[nj]  = (uint32_t)(row >> 1) & 7u;
    }

    for (int t = 0; t < KITER; t++) {
        // stage t%3 (group g_t) complete: committed g0..g_{t+2}, wait leaves <=2
        CP_WAIT2();
        __syncthreads();

        const uint32_t st = sb + (t % 3) * STG_BYTES;
        const uint32_t sAhi = st + A_HI_OFF, sAlo = st + A_LO_OFF;
        const uint32_t sBhi = st + B_HI_OFF, sBlo = st + B_LO_OFF;

#pragma unroll
        for (int k16 = 0; k16 < 2; k16++) {
            const uint32_t kc = (uint32_t)(k16 * 2) + kcq;   // 16B chunk 0..3

            // B fragments for this k16
            uint32_t b_hi[4][2], b_lo[4][2];
#pragma unroll
            for (int nj = 0; nj < 2; nj++) {
                uint32_t off = bLine[nj] + (((bPar[nj] | kc) ^ bSwz[nj]) << 4);
                uint32_t th[4], tl[4];
                LDSM4(th, sBhi + off);
                LDSM4(tl, sBlo + off);
                b_hi[2 * nj][0] = th[0]; b_hi[2 * nj][1] = th[2];
                b_hi[2 * nj + 1][0] = th[1]; b_hi[2 * nj + 1][1] = th[3];
                b_lo[2 * nj][0] = tl[0]; b_lo[2 * nj][1] = tl[2];
                b_lo[2 * nj + 1][0] = tl[1]; b_lo[2 * nj + 1][1] = tl[3];
            }

            // A fragments double-buffered across mi
            uint32_t a_hi[2][4], a_lo[2][4];
            {
                uint32_t off = aLine[0] + (((aPar[0] | kc) ^ aSwz[0]) << 4);
                LDSM4(a_hi[0], sAhi + off);
                LDSM4(a_lo[0], sAlo + off);
            }
#pragma unroll
            for (int mi = 0; mi < 4; mi++) {
                const int cur = mi & 1, nxt = cur ^ 1;
                if (mi < 3) {
                    uint32_t off = aLine[mi + 1] + (((aPar[mi + 1] | kc) ^ aSwz[mi + 1]) << 4);
                    LDSM4(a_hi[nxt], sAhi + off);
                    LDSM4(a_lo[nxt], sAlo + off);
                }
#pragma unroll
                for (int ni = 0; ni < 4; ni++) MMA16816(acc[mi][ni], a_hi[cur], b_hi[ni]);
#pragma unroll
                for (int ni = 0; ni < 4; ni++) MMA16816(acc[mi][ni], a_hi[cur], b_lo[ni]);
#pragma unroll
                for (int ni = 0; ni < 4; ni++) MMA16816(acc[mi][ni], a_lo[cur], b_hi[ni]);
            }
        }

        // all warps done reading stage t%3 -> safe to overwrite with k-tile t+3
        __syncthreads();
        if (t + 3 < KITER) {
            LOAD_STAGE(sb + (t % 3) * STG_BYTES);
        }
        CP_COMMIT();
    }

    // ---- fused cosine epilogue ----
    const int gq = lane >> 2;
    const int tq = lane & 3;

    float yv0[4], yv1[4];
#pragma unroll
    for (int ni = 0; ni < 4; ni++) {
        int n = rowB0 + wn * 32 + ni * 8 + 2 * tq;
        yv0[ni] = g_yn[b * Nq + n];
        yv1[ni] = g_yn[b * Nq + n + 1];
    }

#pragma unroll
    for (int mi = 0; mi < 4; mi++) {
        int mA = rowA0 + wm * 64 + mi * 16 + gq;
        float xA = g_xn[b * Nq + mA];
        float xB = g_xn[b * Nq + mA + 8];
        float* orowA = out + ((size_t)b * Nq + mA) * Nq + rowB0 + wn * 32;
        float* orowB = orowA + 8 * (size_t)Nq;
#pragma unroll
        for (int ni = 0; ni < 4; ni++) {
            float2 vA, vB;
            vA.x = acc[mi][ni][0] / fmaxf(xA * yv0[ni], EPSq);
            vA.y = acc[mi][ni][1] / fmaxf(xA * yv1[ni], EPSq);
            vB.x = acc[mi][ni][2] / fmaxf(xB * yv0[ni], EPSq);
            vB.y = acc[mi][ni][3] / fmaxf(xB * yv1[ni], EPSq);
            *reinterpret_cast<float2*>(orowA + ni * 8 + 2 * tq) = vA;
            *reinterpret_cast<float2*>(orowB + ni * 8 + 2 * tq) = vB;
        }
    }
}

// ---------------------------------------------------------------------------
extern "C" void kernel_launch(void* const* d_in, const int* in_sizes, int n_in,
                              void* d_out, int out_size) {
    const float* x = (const float*)d_in[0];
    const float* y = (const float*)d_in[1];
    float* out = (float*)d_out;

    prep_kernel<<<(Bq * Nq + 7) / 8, 256>>>(x, y);

    cudaFuncSetAttribute(cosine_mma_kernel,
                         cudaFuncAttributeMaxDynamicSharedMemorySize, SMEM_TOTAL);
    dim3 grid(Nq / BNq, Nq / BMq, Bq);   // (16, 16, 8)
    cosine_mma_kernel<<<grid, 256, SMEM_TOTAL>>>(out);
}

// round 9
// speedup vs baseline: 1.6528x; 1.3735x over previous
#include <cuda_runtime.h>
#include <cuda_bf16.h>
#include <cstdint>

// ============================================================================
// out[b,n,m] = <x[b,n,:], y[b,m,:]> / max(||x[b,n]|| * ||y[b,m]||, eps)
//   x, y: [8, 2048, 512] fp32 ; out: [8, 2048, 2048] fp32
//
// Round 9: SINGLE-PASS tf32 mma.sync (m16n8k8), RNA-rounded inputs.
//   3x fewer tensor passes than bf16 Markidis -> tensor floor 171us -> ~114us.
//   CTA 128x128, 256 threads, BK=32 (128B rows, round-4-verified swizzle),
//   3-stage cp.async ring, 2 CTAs/SM, round-8-proven loop structure.
// ============================================================================

#define Bq 8
#define Nq 2048
#define Dq 512
#define EPSq 1e-8f

#define BMq 128
#define BNq 128
#define BKq 32                 // 32 tf32 = 128B per row
#define KITER (Dq / BKq)       // 16

// per-stage: A 16K | B 16K = 32KB; 3 stages = 96KB
#define A_OFF      0
#define B_OFF      16384
#define STG_BYTES  32768
#define SMEM_TOTAL (3 * STG_BYTES)   // 98304

#define ROW32 (32 * Dq)        // 32-row pointer offset (elements)

__device__ float g_xn[Bq * Nq];
__device__ float g_yn[Bq * Nq];
__device__ float g_xt[Bq * Nq * Dq];   // tf32-rounded x (fp32 container)
__device__ float g_yt[Bq * Nq * Dq];   // tf32-rounded y

// ---------------------------------------------------------------------------
__device__ __forceinline__ uint32_t smem_u32(const void* p) {
    uint32_t a;
    asm("{ .reg .u64 t; cvta.to.shared.u64 t, %1; cvt.u32.u64 %0, t; }"
        : "=r"(a) : "l"(p));
    return a;
}

#define CP_ASYNC16(dst, src) \
    asm volatile("cp.async.cg.shared.global [%0], [%1], 16;" \
                 :: "r"(dst), "l"(src) : "memory")
#define CP_COMMIT() asm volatile("cp.async.commit_group;" ::: "memory")
#define CP_WAIT2()  asm volatile("cp.async.wait_group 2;" ::: "memory")

#define LDSM4(r, addr) \
    asm volatile("ldmatrix.sync.aligned.m8n8.x4.shared.b16 {%0,%1,%2,%3}, [%4];" \
                 : "=r"((r)[0]), "=r"((r)[1]), "=r"((r)[2]), "=r"((r)[3]) \
                 : "r"(addr))

#define MMA_TF32(d, a, bf) \
    asm volatile("mma.sync.aligned.m16n8k8.row.col.f32.tf32.tf32.f32 " \
                 "{%0,%1,%2,%3}, {%4,%5,%6,%7}, {%8,%9}, {%0,%1,%2,%3};" \
                 : "+f"((d)[0]), "+f"((d)[1]), "+f"((d)[2]), "+f"((d)[3]) \
                 : "r"((a)[0]), "r"((a)[1]), "r"((a)[2]), "r"((a)[3]), \
                   "r"((bf)[0]), "r"((bf)[1]))

#define CVT_TF32(o, f) \
    asm("cvt.rna.tf32.f32 %0, %1;" : "=r"(o) : "f"(f))

// ---------------------------------------------------------------------------
// Prep: one warp per row: norms (on original fp32) + RNA tf32 rounding.
// ---------------------------------------------------------------------------
__global__ void __launch_bounds__(256) prep_kernel(const float* __restrict__ X,
                                                   const float* __restrict__ Y) {
    int row = blockIdx.x * 8 + (threadIdx.x >> 5);
    int lane = threadIdx.x & 31;
    if (row >= Bq * Nq) return;

    const float4* px = reinterpret_cast<const float4*>(X + (size_t)row * Dq);
    const float4* py = reinterpret_cast<const float4*>(Y + (size_t)row * Dq);

    float sx = 0.f, sy = 0.f;
#pragma unroll
    for (int v = 0; v < 4; v++) {
        int i = v * 32 + lane;
        size_t off = (size_t)row * Dq + (size_t)i * 4;
        {
            float4 a = px[i];
            sx = fmaf(a.x, a.x, sx); sx = fmaf(a.y, a.y, sx);
            sx = fmaf(a.z, a.z, sx); sx = fmaf(a.w, a.w, sx);
            uint4 t;
            CVT_TF32(t.x, a.x); CVT_TF32(t.y, a.y);
            CVT_TF32(t.z, a.z); CVT_TF32(t.w, a.w);
            *reinterpret_cast<uint4*>(g_xt + off) = t;
        }
        {
            float4 a = py[i];
            sy = fmaf(a.x, a.x, sy); sy = fmaf(a.y, a.y, sy);
            sy = fmaf(a.z, a.z, sy); sy = fmaf(a.w, a.w, sy);
            uint4 t;
            CVT_TF32(t.x, a.x); CVT_TF32(t.y, a.y);
            CVT_TF32(t.z, a.z); CVT_TF32(t.w, a.w);
            *reinterpret_cast<uint4*>(g_yt + off) = t;
        }
    }
#pragma unroll
    for (int off = 16; off > 0; off >>= 1) {
        sx += __shfl_xor_sync(0xFFFFFFFFu, sx, off);
        sy += __shfl_xor_sync(0xFFFFFFFFu, sy, off);
    }
    if (lane == 0) {
        g_xn[row] = sqrtf(sx);
        g_yn[row] = sqrtf(sy);
    }
}

// ---------------------------------------------------------------------------
// GEMM kernel. Grid (16,16,8), 256 threads = 8 warps (2x4), warp tile 64x32.
// 2 CTAs per SM. Single-pass tf32.
// ---------------------------------------------------------------------------
__global__ void __launch_bounds__(256, 2) cosine_mma_kernel(float* __restrict__ out) {
    extern __shared__ char smem[];
    const uint32_t sb = smem_u32(smem);

    const int tid = threadIdx.x;
    const int wid = tid >> 5, lane = tid & 31;
    const int wm = wid >> 2;          // 0..1  (64 m-rows)
    const int wn = wid & 3;           // 0..3  (32 n-cols)
    const int tileM = blockIdx.x;
    const int tileN = blockIdx.y;
    const int b = blockIdx.z;
    const int rowA0 = tileN * BMq;
    const int rowB0 = tileM * BNq;

    // ---- cp.async setup: 128B rows, 8x 16B chunks, swizzle c^(r&7) ----
    // thread -> (r0 = tid>>3 in 0..31 step, c0 = tid&7); 4 row-groups of 32.
    const int r0 = tid >> 3;          // 0..31
    const int c0 = tid & 7;
    const uint32_t dA0 = (uint32_t)r0 * 128 + (uint32_t)((c0 ^ (r0 & 7)) << 4);
    // rows r0+32i have same (r&7) -> swizzle term identical; offset += i*4096
    const float* pxt = g_xt + (size_t)(b * Nq + rowA0 + r0) * Dq + c0 * 4;
    const float* pyt = g_yt + (size_t)(b * Nq + rowB0 + r0) * Dq + c0 * 4;

#define LOAD_STAGE(ST) do {                                          \
        CP_ASYNC16((ST) + A_OFF + dA0,         pxt);                 \
        CP_ASYNC16((ST) + A_OFF + dA0 + 4096,  pxt + ROW32);         \
        CP_ASYNC16((ST) + A_OFF + dA0 + 8192,  pxt + 2 * ROW32);     \
        CP_ASYNC16((ST) + A_OFF + dA0 + 12288, pxt + 3 * ROW32);     \
        CP_ASYNC16((ST) + B_OFF + dA0,         pyt);                 \
        CP_ASYNC16((ST) + B_OFF + dA0 + 4096,  pyt + ROW32);         \
        CP_ASYNC16((ST) + B_OFF + dA0 + 8192,  pyt + 2 * ROW32);     \
        CP_ASYNC16((ST) + B_OFF + dA0 + 12288, pyt + 3 * ROW32);     \
        pxt += BKq; pyt += BKq;                                      \
    } while (0)

    float acc[4][4][4];
#pragma unroll
    for (int i = 0; i < 4; i++)
#pragma unroll
        for (int j = 0; j < 4; j++)
#pragma unroll
            for (int r = 0; r < 4; r++) acc[i][j][r] = 0.f;

    // prologue: 3 stages in flight (k-tiles 0,1,2)
    LOAD_STAGE(sb + 0 * STG_BYTES); CP_COMMIT();
    LOAD_STAGE(sb + 1 * STG_BYTES); CP_COMMIT();
    LOAD_STAGE(sb + 2 * STG_BYTES); CP_COMMIT();

    // ---- fragment addressing ----
    // ldmatrix lane roles: row = base + (lane&15), chunk = 2q + (lane>>4)
    const int rowSel = lane & 15;
    const uint32_t hv = (uint32_t)(lane >> 4);   // 0/1

    uint32_t aRowT[4], aSwz[4];
#pragma unroll
    for (int mi = 0; mi < 4; mi++) {
        int row = wm * 64 + mi * 16 + rowSel;
        aRowT[mi] = (uint32_t)row * 128u;
        aSwz[mi]  = (uint32_t)(row & 7);
    }
    uint32_t bRowT[2], bSwz[2];
#pragma unroll
    for (int nj = 0; nj < 2; nj++) {
        int row = wn * 32 + nj * 16 + rowSel;
        bRowT[nj] = (uint32_t)row * 128u;
        bSwz[nj]  = (uint32_t)(row & 7);
    }

    for (int t = 0; t < KITER; t++) {
        CP_WAIT2();
        __syncthreads();

        const uint32_t st = sb + (t % 3) * STG_BYTES;
        const uint32_t sA = st + A_OFF, sB = st + B_OFF;

#pragma unroll
        for (int q = 0; q < 4; q++) {        // four k8 blocks per stage
            const uint32_t chunk = (uint32_t)(2 * q) + hv;   // 16B chunk 0..7

            // B fragments: 2 ldmatrix.x4 -> b-frags for 4 n-blocks
            uint32_t bf[4][2];
#pragma unroll
            for (int nj = 0; nj < 2; nj++) {
                uint32_t off = bRowT[nj] + ((chunk ^ bSwz[nj]) << 4);
                uint32_t tb[4];
                LDSM4(tb, sB + off);
                bf[2 * nj][0] = tb[0]; bf[2 * nj + 1][0] = tb[1];
                bf[2 * nj][1] = tb[2]; bf[2 * nj + 1][1] = tb[3];
            }

            // A fragments double-buffered across mi
            uint32_t af[2][4];
            {
                uint32_t off = aRowT[0] + ((chunk ^ aSwz[0]) << 4);
                LDSM4(af[0], sA + off);
            }
#pragma unroll
            for (int mi = 0; mi < 4; mi++) {
                const int cur = mi & 1, nxt = cur ^ 1;
                if (mi < 3) {
                    uint32_t off = aRowT[mi + 1] + ((chunk ^ aSwz[mi + 1]) << 4);
                    LDSM4(af[nxt], sA + off);
                }
#pragma unroll
                for (int ni = 0; ni < 4; ni++)
                    MMA_TF32(acc[mi][ni], af[cur], bf[ni]);
            }
        }

        __syncthreads();
        if (t + 3 < KITER) {
            LOAD_STAGE(sb + (t % 3) * STG_BYTES);
        }
        CP_COMMIT();
    }

    // ---- fused cosine epilogue ----
    const int gq = lane >> 2;
    const int tq = lane & 3;

    float yv0[4], yv1[4];
#pragma unroll
    for (int ni = 0; ni < 4; ni++) {
        int n = rowB0 + wn * 32 + ni * 8 + 2 * tq;
        yv0[ni] = g_yn[b * Nq + n];
        yv1[ni] = g_yn[b * Nq + n + 1];
    }

#pragma unroll
    for (int mi = 0; mi < 4; mi++) {
        int mA = rowA0 + wm * 64 + mi * 16 + gq;
        float xA = g_xn[b * Nq + mA];
        float xB = g_xn[b * Nq + mA + 8];
        float* orowA = out + ((size_t)b * Nq + mA) * Nq + rowB0 + wn * 32;
        float* orowB = orowA + 8 * (size_t)Nq;
#pragma unroll
        for (int ni = 0; ni < 4; ni++) {
            float2 vA, vB;
            vA.x = acc[mi][ni][0] / fmaxf(xA * yv0[ni], EPSq);
            vA.y = acc[mi][ni][1] / fmaxf(xA * yv1[ni], EPSq);
            vB.x = acc[mi][ni][2] / fmaxf(xB * yv0[ni], EPSq);
            vB.y = acc[mi][ni][3] / fmaxf(xB * yv1[ni], EPSq);
            *reinterpret_cast<float2*>(orowA + ni * 8 + 2 * tq) = vA;
            *reinterpret_cast<float2*>(orowB + ni * 8 + 2 * tq) = vB;
        }
    }
}

// ---------------------------------------------------------------------------
extern "C" void kernel_launch(void* const* d_in, const int* in_sizes, int n_in,
                              void* d_out, int out_size) {
    const float* x = (const float*)d_in[0];
    const float* y = (const float*)d_in[1];
    float* out = (float*)d_out;

    prep_kernel<<<(Bq * Nq + 7) / 8, 256>>>(x, y);

    cudaFuncSetAttribute(cosine_mma_kernel,
                         cudaFuncAttributeMaxDynamicSharedMemorySize, SMEM_TOTAL);
    dim3 grid(Nq / BNq, Nq / BMq, Bq);   // (16, 16, 8)
    cosine_mma_kernel<<<grid, 256, SMEM_TOTAL>>>(out);
}

// round 10
// speedup vs baseline: 1.6554x; 1.0016x over previous
#include <cuda_runtime.h>
#include <cuda_bf16.h>
#include <cstdint>

// ============================================================================
// out[b,n,m] = <x[b,n,:], y[b,m,:]> / max(||x[b,n]|| * ||y[b,m]||, eps)
//   x, y: [8, 2048, 512] fp32 ; out: [8, 2048, 2048] fp32
//
// Round 10: single-pass tf32 (round 9) + full fragment software pipelining:
//   - B fragments double-buffered across q (k8 blocks)
//   - A fragments double-buffered across mi AND across the q boundary
//   Exposed LDSM latency: once per k-iter (post-barrier) instead of 4x.
//   CTA 128x128, 256 threads, BK=32, 3-stage cp.async, 2 CTAs/SM.
// ============================================================================

#define Bq 8
#define Nq 2048
#define Dq 512
#define EPSq 1e-8f

#define BMq 128
#define BNq 128
#define BKq 32                 // 32 tf32 = 128B per row
#define KITER (Dq / BKq)       // 16

#define A_OFF      0
#define B_OFF      16384
#define STG_BYTES  32768
#define SMEM_TOTAL (3 * STG_BYTES)   // 98304

#define ROW32 (32 * Dq)

__device__ float g_xn[Bq * Nq];
__device__ float g_yn[Bq * Nq];
__device__ float g_xt[Bq * Nq * Dq];
__device__ float g_yt[Bq * Nq * Dq];

// ---------------------------------------------------------------------------
__device__ __forceinline__ uint32_t smem_u32(const void* p) {
    uint32_t a;
    asm("{ .reg .u64 t; cvta.to.shared.u64 t, %1; cvt.u32.u64 %0, t; }"
        : "=r"(a) : "l"(p));
    return a;
}

#define CP_ASYNC16(dst, src) \
    asm volatile("cp.async.cg.shared.global [%0], [%1], 16;" \
                 :: "r"(dst), "l"(src) : "memory")
#define CP_COMMIT() asm volatile("cp.async.commit_group;" ::: "memory")
#define CP_WAIT2()  asm volatile("cp.async.wait_group 2;" ::: "memory")

#define LDSM4(r, addr) \
    asm volatile("ldmatrix.sync.aligned.m8n8.x4.shared.b16 {%0,%1,%2,%3}, [%4];" \
                 : "=r"((r)[0]), "=r"((r)[1]), "=r"((r)[2]), "=r"((r)[3]) \
                 : "r"(addr))

#define MMA_TF32(d, a, bf) \
    asm volatile("mma.sync.aligned.m16n8k8.row.col.f32.tf32.tf32.f32 " \
                 "{%0,%1,%2,%3}, {%4,%5,%6,%7}, {%8,%9}, {%0,%1,%2,%3};" \
                 : "+f"((d)[0]), "+f"((d)[1]), "+f"((d)[2]), "+f"((d)[3]) \
                 : "r"((a)[0]), "r"((a)[1]), "r"((a)[2]), "r"((a)[3]), \
                   "r"((bf)[0]), "r"((bf)[1]))

#define CVT_TF32(o, f) \
    asm("cvt.rna.tf32.f32 %0, %1;" : "=r"(o) : "f"(f))

// ---------------------------------------------------------------------------
// Prep: one warp per row: norms (fp32) + RNA tf32 rounding.
// ---------------------------------------------------------------------------
__global__ void __launch_bounds__(256) prep_kernel(const float* __restrict__ X,
                                                   const float* __restrict__ Y) {
    int row = blockIdx.x * 8 + (threadIdx.x >> 5);
    int lane = threadIdx.x & 31;
    if (row >= Bq * Nq) return;

    const float4* px = reinterpret_cast<const float4*>(X + (size_t)row * Dq);
    const float4* py = reinterpret_cast<const float4*>(Y + (size_t)row * Dq);

    float sx = 0.f, sy = 0.f;
#pragma unroll
    for (int v = 0; v < 4; v++) {
        int i = v * 32 + lane;
        size_t off = (size_t)row * Dq + (size_t)i * 4;
        {
            float4 a = px[i];
            sx = fmaf(a.x, a.x, sx); sx = fmaf(a.y, a.y, sx);
            sx = fmaf(a.z, a.z, sx); sx = fmaf(a.w, a.w, sx);
            uint4 t;
            CVT_TF32(t.x, a.x); CVT_TF32(t.y, a.y);
            CVT_TF32(t.z, a.z); CVT_TF32(t.w, a.w);
            *reinterpret_cast<uint4*>(g_xt + off) = t;
        }
        {
            float4 a = py[i];
            sy = fmaf(a.x, a.x, sy); sy = fmaf(a.y, a.y, sy);
            sy = fmaf(a.z, a.z, sy); sy = fmaf(a.w, a.w, sy);
            uint4 t;
            CVT_TF32(t.x, a.x); CVT_TF32(t.y, a.y);
            CVT_TF32(t.z, a.z); CVT_TF32(t.w, a.w);
            *reinterpret_cast<uint4*>(g_yt + off) = t;
        }
    }
#pragma unroll
    for (int off = 16; off > 0; off >>= 1) {
        sx += __shfl_xor_sync(0xFFFFFFFFu, sx, off);
        sy += __shfl_xor_sync(0xFFFFFFFFu, sy, off);
    }
    if (lane == 0) {
        g_xn[row] = sqrtf(sx);
        g_yn[row] = sqrtf(sy);
    }
}

// ---------------------------------------------------------------------------
// GEMM kernel. Grid (16,16,8), 256 threads = 8 warps (2x4), warp tile 64x32.
// 2 CTAs per SM. Single-pass tf32, fully pipelined fragments.
// ---------------------------------------------------------------------------
__global__ void __launch_bounds__(256, 2) cosine_mma_kernel(float* __restrict__ out) {
    extern __shared__ char smem[];
    const uint32_t sb = smem_u32(smem);

    const int tid = threadIdx.x;
    const int wid = tid >> 5, lane = tid & 31;
    const int wm = wid >> 2;          // 0..1
    const int wn = wid & 3;           // 0..3
    const int tileM = blockIdx.x;
    const int tileN = blockIdx.y;
    const int b = blockIdx.z;
    const int rowA0 = tileN * BMq;
    const int rowB0 = tileM * BNq;

    // ---- cp.async setup ----
    const int r0 = tid >> 3;          // 0..31
    const int c0 = tid & 7;
    const uint32_t dA0 = (uint32_t)r0 * 128 + (uint32_t)((c0 ^ (r0 & 7)) << 4);
    const float* pxt = g_xt + (size_t)(b * Nq + rowA0 + r0) * Dq + c0 * 4;
    const float* pyt = g_yt + (size_t)(b * Nq + rowB0 + r0) * Dq + c0 * 4;

#define LOAD_STAGE(ST) do {                                          \
        CP_ASYNC16((ST) + A_OFF + dA0,         pxt);                 \
        CP_ASYNC16((ST) + A_OFF + dA0 + 4096,  pxt + ROW32);         \
        CP_ASYNC16((ST) + A_OFF + dA0 + 8192,  pxt + 2 * ROW32);     \
        CP_ASYNC16((ST) + A_OFF + dA0 + 12288, pxt + 3 * ROW32);     \
        CP_ASYNC16((ST) + B_OFF + dA0,         pyt);                 \
        CP_ASYNC16((ST) + B_OFF + dA0 + 4096,  pyt + ROW32);         \
        CP_ASYNC16((ST) + B_OFF + dA0 + 8192,  pyt + 2 * ROW32);     \
        CP_ASYNC16((ST) + B_OFF + dA0 + 12288, pyt + 3 * ROW32);     \
        pxt += BKq; pyt += BKq;                                      \
    } while (0)

    float acc[4][4][4];
#pragma unroll
    for (int i = 0; i < 4; i++)
#pragma unroll
        for (int j = 0; j < 4; j++)
#pragma unroll
            for (int r = 0; r < 4; r++) acc[i][j][r] = 0.f;

    LOAD_STAGE(sb + 0 * STG_BYTES); CP_COMMIT();
    LOAD_STAGE(sb + 1 * STG_BYTES); CP_COMMIT();
    LOAD_STAGE(sb + 2 * STG_BYTES); CP_COMMIT();

    // ---- fragment addressing ----
    const int rowSel = lane & 15;
    const uint32_t hv = (uint32_t)(lane >> 4);   // 0/1

    uint32_t aRowT[4], aSwz[4];
#pragma unroll
    for (int mi = 0; mi < 4; mi++) {
        int row = wm * 64 + mi * 16 + rowSel;
        aRowT[mi] = (uint32_t)row * 128u;
        aSwz[mi]  = (uint32_t)(row & 7);
    }
    uint32_t bRowT[2], bSwz[2];
#pragma unroll
    for (int nj = 0; nj < 2; nj++) {
        int row = wn * 32 + nj * 16 + rowSel;
        bRowT[nj] = (uint32_t)row * 128u;
        bSwz[nj]  = (uint32_t)(row & 7);
    }

    for (int t = 0; t < KITER; t++) {
        CP_WAIT2();
        __syncthreads();

        const uint32_t st = sb + (t % 3) * STG_BYTES;
        const uint32_t sA = st + A_OFF, sB = st + B_OFF;

        // fragment buffers: af double-buffered over a global (q*4+mi) index,
        // bf double-buffered over q.
        uint32_t af[2][4];
        uint32_t bf[2][4][2];

        // preload q=0 fragments (the only exposed LDSM latency per k-iter)
        {
            const uint32_t chunk0 = hv;
#pragma unroll
            for (int nj = 0; nj < 2; nj++) {
                uint32_t off = bRowT[nj] + ((chunk0 ^ bSwz[nj]) << 4);
                uint32_t tb[4];
                LDSM4(tb, sB + off);
                bf[0][2 * nj][0] = tb[0]; bf[0][2 * nj + 1][0] = tb[1];
                bf[0][2 * nj][1] = tb[2]; bf[0][2 * nj + 1][1] = tb[3];
            }
            uint32_t off = aRowT[0] + ((chunk0 ^ aSwz[0]) << 4);
            LDSM4(af[0], sA + off);
        }

#pragma unroll
        for (int q = 0; q < 4; q++) {
            const int cq = q & 1;
            const uint32_t chunkN = (uint32_t)(2 * (q + 1)) + hv;  // next q's chunk
            const uint32_t chunkC = (uint32_t)(2 * q) + hv;        // current chunk

#pragma unroll
            for (int mi = 0; mi < 4; mi++) {
                const int idx = q * 4 + mi;
                const int cur = idx & 1, nxt = cur ^ 1;

                // prefetch next A fragment (next mi, or mi=0 of next q)
                if (idx < 15) {
                    const int miN = (mi + 1) & 3;
                    const uint32_t ch = (mi == 3) ? chunkN : chunkC;
                    uint32_t off = aRowT[miN] + ((ch ^ aSwz[miN]) << 4);
                    LDSM4(af[nxt], sA + off);
                }
                // prefetch next q's B fragments early in this q
                if (q < 3 && mi < 2) {
                    const int nj = mi;     // mi=0 -> nj0, mi=1 -> nj1
                    uint32_t off = bRowT[nj] + ((chunkN ^ bSwz[nj]) << 4);
                    uint32_t tb[4];
                    LDSM4(tb, sB + off);
                    bf[cq ^ 1][2 * nj][0] = tb[0]; bf[cq ^ 1][2 * nj + 1][0] = tb[1];
                    bf[cq ^ 1][2 * nj][1] = tb[2]; bf[cq ^ 1][2 * nj + 1][1] = tb[3];
                }
#pragma unroll
                for (int ni = 0; ni < 4; ni++)
                    MMA_TF32(acc[mi][ni], af[cur], bf[cq][ni]);
            }
        }

        __syncthreads();
        if (t + 3 < KITER) {
            LOAD_STAGE(sb + (t % 3) * STG_BYTES);
        }
        CP_COMMIT();
    }

    // ---- fused cosine epilogue ----
    const int gq = lane >> 2;
    const int tq = lane & 3;

    float yv0[4], yv1[4];
#pragma unroll
    for (int ni = 0; ni < 4; ni++) {
        int n = rowB0 + wn * 32 + ni * 8 + 2 * tq;
        yv0[ni] = g_yn[b * Nq + n];
        yv1[ni] = g_yn[b * Nq + n + 1];
    }

#pragma unroll
    for (int mi = 0; mi < 4; mi++) {
        int mA = rowA0 + wm * 64 + mi * 16 + gq;
        float xA = g_xn[b * Nq + mA];
        float xB = g_xn[b * Nq + mA + 8];
        float* orowA = out + ((size_t)b * Nq + mA) * Nq + rowB0 + wn * 32;
        float* orowB = orowA + 8 * (size_t)Nq;
#pragma unroll
        for (int ni = 0; ni < 4; ni++) {
            float2 vA, vB;
            vA.x = acc[mi][ni][0] / fmaxf(xA * yv0[ni], EPSq);
            vA.y = acc[mi][ni][1] / fmaxf(xA * yv1[ni], EPSq);
            vB.x = acc[mi][ni][2] / fmaxf(xB * yv0[ni], EPSq);
            vB.y = acc[mi][ni][3] / fmaxf(xB * yv1[ni], EPSq);
            *reinterpret_cast<float2*>(orowA + ni * 8 + 2 * tq) = vA;
            *reinterpret_cast<float2*>(orowB + ni * 8 + 2 * tq) = vB;
        }
    }
}

// ---------------------------------------------------------------------------
extern "C" void kernel_launch(void* const* d_in, const int* in_sizes, int n_in,
                              void* d_out, int out_size) {
    const float* x = (const float*)d_in[0];
    const float* y = (const float*)d_in[1];
    float* out = (float*)d_out;

    prep_kernel<<<(Bq * Nq + 7) / 8, 256>>>(x, y);

    cudaFuncSetAttribute(cosine_mma_kernel,
                         cudaFuncAttributeMaxDynamicSharedMemorySize, SMEM_TOTAL);
    dim3 grid(Nq / BNq, Nq / BMq, Bq);   // (16, 16, 8)
    cosine_mma_kernel<<<grid, 256, SMEM_TOTAL>>>(out);
}

// round 11
// speedup vs baseline: 2.6022x; 1.5719x over previous
#include <cuda_runtime.h>
#include <cuda_fp16.h>
#include <cstdint>

// ============================================================================
// out[b,n,m] = <x[b,n,:], y[b,m,:]> / max(||x[b,n]|| * ||y[b,m]||, eps)
//   x, y: [8, 2048, 512] fp32 ; out: [8, 2048, 2048] fp32
//
// Round 11: SINGLE-PASS fp16 m16n8k16 (fp32 accum).
//   fp16 mantissa (10 explicit bits) == tf32 mantissa -> same rel_err (~3e-4)
//   at HALF the tensor instructions and HALF the operand bytes of round 9/10.
//   Structure = round-8-proven: CTA 128x128, 256 thr, BK=32, swz64 layout,
//   3-stage cp.async ring (16KB/stage), 2 CTAs/SM, fused cosine epilogue.
// ============================================================================

#define Bq 8
#define Nq 2048
#define Dq 512
#define EPSq 1e-8f

#define BMq 128
#define BNq 128
#define BKq 32                 // 32 fp16 = 64B per row
#define KITER (Dq / BKq)       // 16

// per-stage: A 8K | B 8K = 16KB; 3 stages = 48KB
#define A_OFF      0
#define B_OFF      8192
#define STG_BYTES  16384
#define SMEM_TOTAL (3 * STG_BYTES)   // 49152

#define ROW64 (64 * Dq)        // 64-row pointer offset (elements)

__device__ float g_xn[Bq * Nq];
__device__ float g_yn[Bq * Nq];
__device__ __half g_xh[Bq * Nq * Dq];
__device__ __half g_yh[Bq * Nq * Dq];

// ---------------------------------------------------------------------------
__device__ __forceinline__ uint32_t smem_u32(const void* p) {
    uint32_t a;
    asm("{ .reg .u64 t; cvta.to.shared.u64 t, %1; cvt.u32.u64 %0, t; }"
        : "=r"(a) : "l"(p));
    return a;
}

#define CP_ASYNC16(dst, src) \
    asm volatile("cp.async.cg.shared.global [%0], [%1], 16;" \
                 :: "r"(dst), "l"(src) : "memory")
#define CP_COMMIT() asm volatile("cp.async.commit_group;" ::: "memory")
#define CP_WAIT2()  asm volatile("cp.async.wait_group 2;" ::: "memory")

#define LDSM4(r, addr) \
    asm volatile("ldmatrix.sync.aligned.m8n8.x4.shared.b16 {%0,%1,%2,%3}, [%4];" \
                 : "=r"((r)[0]), "=r"((r)[1]), "=r"((r)[2]), "=r"((r)[3]) \
                 : "r"(addr))

#define MMA_F16(d, a, bf) \
    asm volatile("mma.sync.aligned.m16n8k16.row.col.f32.f16.f16.f32 " \
                 "{%0,%1,%2,%3}, {%4,%5,%6,%7}, {%8,%9}, {%0,%1,%2,%3};" \
                 : "+f"((d)[0]), "+f"((d)[1]), "+f"((d)[2]), "+f"((d)[3]) \
                 : "r"((a)[0]), "r"((a)[1]), "r"((a)[2]), "r"((a)[3]), \
                   "r"((bf)[0]), "r"((bf)[1]))

// paired-row swizzle for 64B rows: line = r>>1 (128B), ce = (r&1)*4 + c
__device__ __forceinline__ uint32_t swz64(int r, int c) {
    uint32_t line = (uint32_t)r >> 1;
    uint32_t ce = (((uint32_t)r & 1u) << 2) | (uint32_t)c;
    return line * 128u + ((ce ^ (line & 7u)) << 4);
}

// ---------------------------------------------------------------------------
// Prep: one warp per row: norms (fp32 exact) + fp16 conversion.
// ---------------------------------------------------------------------------
__global__ void __launch_bounds__(256) prep_kernel(const float* __restrict__ X,
                                                   const float* __restrict__ Y) {
    int row = blockIdx.x * 8 + (threadIdx.x >> 5);
    int lane = threadIdx.x & 31;
    if (row >= Bq * Nq) return;

    const float4* px = reinterpret_cast<const float4*>(X + (size_t)row * Dq);
    const float4* py = reinterpret_cast<const float4*>(Y + (size_t)row * Dq);

    float sx = 0.f, sy = 0.f;
#pragma unroll
    for (int v = 0; v < 4; v++) {
        int i = v * 32 + lane;
        size_t off = (size_t)row * Dq + (size_t)i * 4;
        {
            float4 a = px[i];
            sx = fmaf(a.x, a.x, sx); sx = fmaf(a.y, a.y, sx);
            sx = fmaf(a.z, a.z, sx); sx = fmaf(a.w, a.w, sx);
            __half2 h0 = __float22half2_rn(make_float2(a.x, a.y));
            __half2 h1 = __float22half2_rn(make_float2(a.z, a.w));
            *reinterpret_cast<__half2*>(g_xh + off)     = h0;
            *reinterpret_cast<__half2*>(g_xh + off + 2) = h1;
        }
        {
            float4 a = py[i];
            sy = fmaf(a.x, a.x, sy); sy = fmaf(a.y, a.y, sy);
            sy = fmaf(a.z, a.z, sy); sy = fmaf(a.w, a.w, sy);
            __half2 h0 = __float22half2_rn(make_float2(a.x, a.y));
            __half2 h1 = __float22half2_rn(make_float2(a.z, a.w));
            *reinterpret_cast<__half2*>(g_yh + off)     = h0;
            *reinterpret_cast<__half2*>(g_yh + off + 2) = h1;
        }
    }
#pragma unroll
    for (int off = 16; off > 0; off >>= 1) {
        sx += __shfl_xor_sync(0xFFFFFFFFu, sx, off);
        sy += __shfl_xor_sync(0xFFFFFFFFu, sy, off);
    }
    if (lane == 0) {
        g_xn[row] = sqrtf(sx);
        g_yn[row] = sqrtf(sy);
    }
}

// ---------------------------------------------------------------------------
// GEMM kernel. Grid (16,16,8), 256 threads = 8 warps (2x4), warp tile 64x32.
// 2 CTAs per SM. Single-pass fp16.
// ---------------------------------------------------------------------------
__global__ void __launch_bounds__(256, 2) cosine_mma_kernel(float* __restrict__ out) {
    extern __shared__ char smem[];
    const uint32_t sb = smem_u32(smem);

    const int tid = threadIdx.x;
    const int wid = tid >> 5, lane = tid & 31;
    const int wm = wid >> 2;          // 0..1  (64 m-rows)
    const int wn = wid & 3;           // 0..3  (32 n-cols)
    const int tileM = blockIdx.x;
    const int tileN = blockIdx.y;
    const int b = blockIdx.z;
    const int rowA0 = tileN * BMq;
    const int rowB0 = tileM * BNq;

    // ---- cp.async setup: 128 rows x 4 chunks(16B) per operand, 2/thread ----
    const int r0 = tid >> 2;          // 0..63
    const int c0 = tid & 3;
    const uint32_t d0 = swz64(r0, c0);
    const uint32_t d1 = swz64(r0 + 64, c0);
    const __half* pxh = g_xh + (size_t)(b * Nq + rowA0 + r0) * Dq + c0 * 8;
    const __half* pyh = g_yh + (size_t)(b * Nq + rowB0 + r0) * Dq + c0 * 8;

#define LOAD_STAGE(ST) do {                                          \
        CP_ASYNC16((ST) + A_OFF + d0, pxh);                          \
        CP_ASYNC16((ST) + A_OFF + d1, pxh + ROW64);                  \
        CP_ASYNC16((ST) + B_OFF + d0, pyh);                          \
        CP_ASYNC16((ST) + B_OFF + d1, pyh + ROW64);                  \
        pxh += BKq; pyh += BKq;                                      \
    } while (0)

    float acc[4][4][4];
#pragma unroll
    for (int i = 0; i < 4; i++)
#pragma unroll
        for (int j = 0; j < 4; j++)
#pragma unroll
            for (int r = 0; r < 4; r++) acc[i][j][r] = 0.f;

    // prologue: 3 stages in flight (k-tiles 0,1,2)
    LOAD_STAGE(sb + 0 * STG_BYTES); CP_COMMIT();
    LOAD_STAGE(sb + 1 * STG_BYTES); CP_COMMIT();
    LOAD_STAGE(sb + 2 * STG_BYTES); CP_COMMIT();

    // ---- fragment addressing (round-5/8-verified swz64 layout) ----
    const int rowSel = (lane & 7) + (((lane >> 3) & 1) << 3);  // 0..15
    const uint32_t kcq = (uint32_t)(lane >> 4);                // 0/1

    uint32_t aLine[4], aPar[4], aSwz[4];
#pragma unroll
    for (int mi = 0; mi < 4; mi++) {
        int row = wm * 64 + mi * 16 + rowSel;
        aLine[mi] = (uint32_t)(row >> 1) * 128u;
        aPar[mi]  = ((uint32_t)row & 1u) << 2;
        aSwz[mi]  = (uint32_t)(row >> 1) & 7u;
    }
    uint32_t bLine[2], bPar[2], bSwz[2];
#pragma unroll
    for (int nj = 0; nj < 2; nj++) {
        int row = wn * 32 + nj * 16 + rowSel;
        bLine[nj] = (uint32_t)(row >> 1) * 128u;
        bPar[nj]  = ((uint32_t)row & 1u) << 2;
        bSwz[nj]  = (uint32_t)(row >> 1) & 7u;
    }

    for (int t = 0; t < KITER; t++) {
        CP_WAIT2();
        __syncthreads();

        const uint32_t st = sb + (t % 3) * STG_BYTES;
        const uint32_t sA = st + A_OFF, sB = st + B_OFF;

#pragma unroll
        for (int k16 = 0; k16 < 2; k16++) {
            const uint32_t kc = (uint32_t)(k16 * 2) + kcq;   // 16B chunk 0..3

            // B fragments for this k16
            uint32_t bf[4][2];
#pragma unroll
            for (int nj = 0; nj < 2; nj++) {
                uint32_t off = bLine[nj] + (((bPar[nj] | kc) ^ bSwz[nj]) << 4);
                uint32_t tb[4];
                LDSM4(tb, sB + off);
                bf[2 * nj][0] = tb[0]; bf[2 * nj][1] = tb[2];
                bf[2 * nj + 1][0] = tb[1]; bf[2 * nj + 1][1] = tb[3];
            }

            // A fragments double-buffered across mi
            uint32_t af[2][4];
            {
                uint32_t off = aLine[0] + (((aPar[0] | kc) ^ aSwz[0]) << 4);
                LDSM4(af[0], sA + off);
            }
#pragma unroll
            for (int mi = 0; mi < 4; mi++) {
                const int cur = mi & 1, nxt = cur ^ 1;
                if (mi < 3) {
                    uint32_t off = aLine[mi + 1] + (((aPar[mi + 1] | kc) ^ aSwz[mi + 1]) << 4);
                    LDSM4(af[nxt], sA + off);
                }
#pragma unroll
                for (int ni = 0; ni < 4; ni++)
                    MMA_F16(acc[mi][ni], af[cur], bf[ni]);
            }
        }

        __syncthreads();
        if (t + 3 < KITER) {
            LOAD_STAGE(sb + (t % 3) * STG_BYTES);
        }
        CP_COMMIT();
    }

    // ---- fused cosine epilogue ----
    const int gq = lane >> 2;
    const int tq = lane & 3;

    float yv0[4], yv1[4];
#pragma unroll
    for (int ni = 0; ni < 4; ni++) {
        int n = rowB0 + wn * 32 + ni * 8 + 2 * tq;
        yv0[ni] = g_yn[b * Nq + n];
        yv1[ni] = g_yn[b * Nq + n + 1];
    }

#pragma unroll
    for (int mi = 0; mi < 4; mi++) {
        int mA = rowA0 + wm * 64 + mi * 16 + gq;
        float xA = g_xn[b * Nq + mA];
        float xB = g_xn[b * Nq + mA + 8];
        float* orowA = out + ((size_t)b * Nq + mA) * Nq + rowB0 + wn * 32;
        float* orowB = orowA + 8 * (size_t)Nq;
#pragma unroll
        for (int ni = 0; ni < 4; ni++) {
            float2 vA, vB;
            vA.x = acc[mi][ni][0] / fmaxf(xA * yv0[ni], EPSq);
            vA.y = acc[mi][ni][1] / fmaxf(xA * yv1[ni], EPSq);
            vB.x = acc[mi][ni][2] / fmaxf(xB * yv0[ni], EPSq);
            vB.y = acc[mi][ni][3] / fmaxf(xB * yv1[ni], EPSq);
            *reinterpret_cast<float2*>(orowA + ni * 8 + 2 * tq) = vA;
            *reinterpret_cast<float2*>(orowB + ni * 8 + 2 * tq) = vB;
        }
    }
}

// ---------------------------------------------------------------------------
extern "C" void kernel_launch(void* const* d_in, const int* in_sizes, int n_in,
                              void* d_out, int out_size) {
    const float* x = (const float*)d_in[0];
    const float* y = (const float*)d_in[1];
    float* out = (float*)d_out;

    prep_kernel<<<(Bq * Nq + 7) / 8, 256>>>(x, y);

    cudaFuncSetAttribute(cosine_mma_kernel,
                         cudaFuncAttributeMaxDynamicSharedMemorySize, SMEM_TOTAL);
    dim3 grid(Nq / BNq, Nq / BMq, Bq);   // (16, 16, 8)
    cosine_mma_kernel<<<grid, 256, SMEM_TOTAL>>>(out);
}

// round 12
// speedup vs baseline: 2.7518x; 1.0575x over previous
#include <cuda_runtime.h>
#include <cuda_fp16.h>
#include <cstdint>

// ============================================================================
// out[b,n,m] = <x[b,n,:], y[b,m,:]> / max(||x[b,n]|| * ||y[b,m]||, eps)
//   x, y: [8, 2048, 512] fp32 ; out: [8, 2048, 2048] fp32
//
// Round 12: single-pass fp16 (R11 math), concurrency push:
//   - CTA 128x64, 128 threads (4 warps 2x2, warp tile 64x32 unchanged)
//   - 12KB/stage x 3 -> 4 independent CTAs/SM (barrier/epilogue hiding)
//   - fully precomputed LDSM smem offsets (1 ADD per LDSM in the loop)
// ============================================================================

#define Bq 8
#define Nq 2048
#define Dq 512
#define EPSq 1e-8f

#define BMq 128
#define BNq 64
#define BKq 32                 // 32 fp16 = 64B per row
#define KITER (Dq / BKq)       // 16

// per-stage: A 8K | B 4K = 12KB; 3 stages = 36KB
#define A_OFF      0
#define B_OFF      8192
#define STG_BYTES  12288
#define SMEM_TOTAL (3 * STG_BYTES)   // 36864

#define ROW32 (32 * Dq)        // 32-row pointer offset (elements)

__device__ float g_xn[Bq * Nq];
__device__ float g_yn[Bq * Nq];
__device__ __half g_xh[Bq * Nq * Dq];
__device__ __half g_yh[Bq * Nq * Dq];

// ---------------------------------------------------------------------------
__device__ __forceinline__ uint32_t smem_u32(const void* p) {
    uint32_t a;
    asm("{ .reg .u64 t; cvta.to.shared.u64 t, %1; cvt.u32.u64 %0, t; }"
        : "=r"(a) : "l"(p));
    return a;
}

#define CP_ASYNC16(dst, src) \
    asm volatile("cp.async.cg.shared.global [%0], [%1], 16;" \
                 :: "r"(dst), "l"(src) : "memory")
#define CP_COMMIT() asm volatile("cp.async.commit_group;" ::: "memory")
#define CP_WAIT2()  asm volatile("cp.async.wait_group 2;" ::: "memory")

#define LDSM4(r, addr) \
    asm volatile("ldmatrix.sync.aligned.m8n8.x4.shared.b16 {%0,%1,%2,%3}, [%4];" \
                 : "=r"((r)[0]), "=r"((r)[1]), "=r"((r)[2]), "=r"((r)[3]) \
                 : "r"(addr))

#define MMA_F16(d, a, bf) \
    asm volatile("mma.sync.aligned.m16n8k16.row.col.f32.f16.f16.f32 " \
                 "{%0,%1,%2,%3}, {%4,%5,%6,%7}, {%8,%9}, {%0,%1,%2,%3};" \
                 : "+f"((d)[0]), "+f"((d)[1]), "+f"((d)[2]), "+f"((d)[3]) \
                 : "r"((a)[0]), "r"((a)[1]), "r"((a)[2]), "r"((a)[3]), \
                   "r"((bf)[0]), "r"((bf)[1]))

// paired-row swizzle for 64B rows: line = r>>1 (128B), ce = (r&1)*4 + c
__device__ __forceinline__ uint32_t swz64(int r, int c) {
    uint32_t line = (uint32_t)r >> 1;
    uint32_t ce = (((uint32_t)r & 1u) << 2) | (uint32_t)c;
    return line * 128u + ((ce ^ (line & 7u)) << 4);
}

// ---------------------------------------------------------------------------
// Prep: one warp per row: norms (fp32 exact) + fp16 conversion.
// ---------------------------------------------------------------------------
__global__ void __launch_bounds__(256) prep_kernel(const float* __restrict__ X,
                                                   const float* __restrict__ Y) {
    int row = blockIdx.x * 8 + (threadIdx.x >> 5);
    int lane = threadIdx.x & 31;
    if (row >= Bq * Nq) return;

    const float4* px = reinterpret_cast<const float4*>(X + (size_t)row * Dq);
    const float4* py = reinterpret_cast<const float4*>(Y + (size_t)row * Dq);

    float sx = 0.f, sy = 0.f;
#pragma unroll
    for (int v = 0; v < 4; v++) {
        int i = v * 32 + lane;
        size_t off = (size_t)row * Dq + (size_t)i * 4;
        {
            float4 a = px[i];
            sx = fmaf(a.x, a.x, sx); sx = fmaf(a.y, a.y, sx);
            sx = fmaf(a.z, a.z, sx); sx = fmaf(a.w, a.w, sx);
            __half2 h0 = __float22half2_rn(make_float2(a.x, a.y));
            __half2 h1 = __float22half2_rn(make_float2(a.z, a.w));
            *reinterpret_cast<__half2*>(g_xh + off)     = h0;
            *reinterpret_cast<__half2*>(g_xh + off + 2) = h1;
        }
        {
            float4 a = py[i];
            sy = fmaf(a.x, a.x, sy); sy = fmaf(a.y, a.y, sy);
            sy = fmaf(a.z, a.z, sy); sy = fmaf(a.w, a.w, sy);
            __half2 h0 = __float22half2_rn(make_float2(a.x, a.y));
            __half2 h1 = __float22half2_rn(make_float2(a.z, a.w));
            *reinterpret_cast<__half2*>(g_yh + off)     = h0;
            *reinterpret_cast<__half2*>(g_yh + off + 2) = h1;
        }
    }
#pragma unroll
    for (int off = 16; off > 0; off >>= 1) {
        sx += __shfl_xor_sync(0xFFFFFFFFu, sx, off);
        sy += __shfl_xor_sync(0xFFFFFFFFu, sy, off);
    }
    if (lane == 0) {
        g_xn[row] = sqrtf(sx);
        g_yn[row] = sqrtf(sy);
    }
}

// ---------------------------------------------------------------------------
// GEMM kernel. Grid (32,16,8) = 4096 CTAs, 128 threads = 4 warps (2x2),
// warp tile 64x32. 4 CTAs per SM. Single-pass fp16.
// ---------------------------------------------------------------------------
__global__ void __launch_bounds__(128, 4) cosine_mma_kernel(float* __restrict__ out) {
    extern __shared__ char smem[];
    const uint32_t sb = smem_u32(smem);

    const int tid = threadIdx.x;
    const int wid = tid >> 5, lane = tid & 31;
    const int wm = wid >> 1;          // 0..1  (64 m-rows)
    const int wn = wid & 1;           // 0..1  (32 n-cols)
    const int tileM = blockIdx.x;     // y tile (64 rows)
    const int tileN = blockIdx.y;     // x tile (128 rows)
    const int b = blockIdx.z;
    const int rowA0 = tileN * BMq;
    const int rowB0 = tileM * BNq;

    // ---- cp.async setup: A 128 rows x 4 chunks, B 64 rows x 4 chunks ----
    const int r0 = tid >> 2;          // 0..31
    const int c0 = tid & 3;
    const uint32_t d0 = swz64(r0, c0);   // rows r0+32i: offset += i*2048
    const __half* pxh = g_xh + (size_t)(b * Nq + rowA0 + r0) * Dq + c0 * 8;
    const __half* pyh = g_yh + (size_t)(b * Nq + rowB0 + r0) * Dq + c0 * 8;

#define LOAD_STAGE(ST) do {                                          \
        CP_ASYNC16((ST) + A_OFF + d0,        pxh);                   \
        CP_ASYNC16((ST) + A_OFF + d0 + 2048, pxh + ROW32);           \
        CP_ASYNC16((ST) + A_OFF + d0 + 4096, pxh + 2 * ROW32);       \
        CP_ASYNC16((ST) + A_OFF + d0 + 6144, pxh + 3 * ROW32);       \
        CP_ASYNC16((ST) + B_OFF + d0,        pyh);                   \
        CP_ASYNC16((ST) + B_OFF + d0 + 2048, pyh + ROW32);           \
        pxh += BKq; pyh += BKq;                                      \
    } while (0)

    float acc[4][4][4];
#pragma unroll
    for (int i = 0; i < 4; i++)
#pragma unroll
        for (int j = 0; j < 4; j++)
#pragma unroll
            for (int r = 0; r < 4; r++) acc[i][j][r] = 0.f;

    // prologue: 3 stages in flight (k-tiles 0,1,2)
    LOAD_STAGE(sb + 0 * STG_BYTES); CP_COMMIT();
    LOAD_STAGE(sb + 1 * STG_BYTES); CP_COMMIT();
    LOAD_STAGE(sb + 2 * STG_BYTES); CP_COMMIT();

    // ---- fully precomputed fragment smem offsets (relative to stage base) ----
    const int rowSel = (lane & 7) + (((lane >> 3) & 1) << 3);  // 0..15
    const uint32_t kcq = (uint32_t)(lane >> 4);                // 0/1

    uint32_t aOff[4][2], bOff[2][2];
#pragma unroll
    for (int mi = 0; mi < 4; mi++) {
        int row = wm * 64 + mi * 16 + rowSel;
        uint32_t line = (uint32_t)(row >> 1);
        uint32_t par  = ((uint32_t)row & 1u) << 2;
#pragma unroll
        for (int k16 = 0; k16 < 2; k16++) {
            uint32_t kc = (uint32_t)(k16 * 2) + kcq;
            aOff[mi][k16] = A_OFF + line * 128u + (((par | kc) ^ (line & 7u)) << 4);
        }
    }
#pragma unroll
    for (int nj = 0; nj < 2; nj++) {
        int row = wn * 32 + nj * 16 + rowSel;
        uint32_t line = (uint32_t)(row >> 1);
        uint32_t par  = ((uint32_t)row & 1u) << 2;
#pragma unroll
        for (int k16 = 0; k16 < 2; k16++) {
            uint32_t kc = (uint32_t)(k16 * 2) + kcq;
            bOff[nj][k16] = B_OFF + line * 128u + (((par | kc) ^ (line & 7u)) << 4);
        }
    }

    for (int t = 0; t < KITER; t++) {
        CP_WAIT2();
        __syncthreads();

        const uint32_t st = sb + (t % 3) * STG_BYTES;

#pragma unroll
        for (int k16 = 0; k16 < 2; k16++) {
            // B fragments for this k16
            uint32_t bf[4][2];
#pragma unroll
            for (int nj = 0; nj < 2; nj++) {
                uint32_t tb[4];
                LDSM4(tb, st + bOff[nj][k16]);
                bf[2 * nj][0] = tb[0]; bf[2 * nj][1] = tb[2];
                bf[2 * nj + 1][0] = tb[1]; bf[2 * nj + 1][1] = tb[3];
            }

            // A fragments double-buffered across mi
            uint32_t af[2][4];
            LDSM4(af[0], st + aOff[0][k16]);
#pragma unroll
            for (int mi = 0; mi < 4; mi++) {
                const int cur = mi & 1, nxt = cur ^ 1;
                if (mi < 3) {
                    LDSM4(af[nxt], st + aOff[mi + 1][k16]);
                }
#pragma unroll
                for (int ni = 0; ni < 4; ni++)
                    MMA_F16(acc[mi][ni], af[cur], bf[ni]);
            }
        }

        __syncthreads();
        if (t + 3 < KITER) {
            LOAD_STAGE(sb + (t % 3) * STG_BYTES);
        }
        CP_COMMIT();
    }

    // ---- fused cosine epilogue ----
    const int gq = lane >> 2;
    const int tq = lane & 3;

    float yv0[4], yv1[4];
#pragma unroll
    for (int ni = 0; ni < 4; ni++) {
        int n = rowB0 + wn * 32 + ni * 8 + 2 * tq;
        yv0[ni] = g_yn[b * Nq + n];
        yv1[ni] = g_yn[b * Nq + n + 1];
    }

#pragma unroll
    for (int mi = 0; mi < 4; mi++) {
        int mA = rowA0 + wm * 64 + mi * 16 + gq;
        float xA = g_xn[b * Nq + mA];
        float xB = g_xn[b * Nq + mA + 8];
        float* orowA = out + ((size_t)b * Nq + mA) * Nq + rowB0 + wn * 32;
        float* orowB = orowA + 8 * (size_t)Nq;
#pragma unroll
        for (int ni = 0; ni < 4; ni++) {
            float2 vA, vB;
            vA.x = acc[mi][ni][0] / fmaxf(xA * yv0[ni], EPSq);
            vA.y = acc[mi][ni][1] / fmaxf(xA * yv1[ni], EPSq);
            vB.x = acc[mi][ni][2] / fmaxf(xB * yv0[ni], EPSq);
            vB.y = acc[mi][ni][3] / fmaxf(xB * yv1[ni], EPSq);
            *reinterpret_cast<float2*>(orowA + ni * 8 + 2 * tq) = vA;
            *reinterpret_cast<float2*>(orowB + ni * 8 + 2 * tq) = vB;
        }
    }
}

// ---------------------------------------------------------------------------
extern "C" void kernel_launch(void* const* d_in, const int* in_sizes, int n_in,
                              void* d_out, int out_size) {
    const float* x = (const float*)d_in[0];
    const float* y = (const float*)d_in[1];
    float* out = (float*)d_out;

    prep_kernel<<<(Bq * Nq + 7) / 8, 256>>>(x, y);

    cudaFuncSetAttribute(cosine_mma_kernel,
                         cudaFuncAttributeMaxDynamicSharedMemorySize, SMEM_TOTAL);
    dim3 grid(Nq / BNq, Nq / BMq, Bq);   // (32, 16, 8)
    cosine_mma_kernel<<<grid, 128, SMEM_TOTAL>>>(out);
}